// round 9
// baseline (speedup 1.0000x reference)
#include <cuda_runtime.h>
#include <cuda_bf16.h>
#include <cstdint>

#define HW_  4096
#define C_   256
#define B_   4
#define NT   512

// ---------------- scratch (__device__ globals per allocation rules) --------
__device__ __align__(1024) __nv_bfloat16 g_refTh[B_ * HW_ * C_]; // [b*4096+pos][ci]
__device__ __align__(1024) __nv_bfloat16 g_refTl[B_ * HW_ * C_];
__device__ __align__(1024) __nv_bfloat16 g_wh[2 * 9 * C_ * C_];  // [w][s][co][ci]
__device__ __align__(1024) __nv_bfloat16 g_wl[2 * 9 * C_ * C_];
__device__ __align__(1024) __nv_bfloat16 g_x1th[B_ * HW_ * C_]; // [b*4096+pos][c]
__device__ __align__(1024) __nv_bfloat16 g_x1tl[B_ * HW_ * C_];
__device__ __align__(1024) __nv_bfloat16 g_Vh[B_ * C_ * HW_];   // [b][c][pos]
__device__ __align__(1024) __nv_bfloat16 g_Vl[B_ * C_ * HW_];
__device__ __align__(1024) __nv_bfloat16 g_Eh[(size_t)B_ * HW_ * HW_]; // exp(S-mx) hi
__device__ __align__(1024) __nv_bfloat16 g_El[(size_t)B_ * HW_ * HW_]; // exp(S-mx) lo
__device__ float g_S[(size_t)B_ * HW_ * HW_];
__device__ float g_rcp[B_ * HW_];

// ---------------- smem: 3 pipeline stages + aux ----------------------------
// stage s at s*65536: Ah +0, Al +16K, Bh +32K, Bl +48K (128 rows x 128B, SW128)
// epilogue fp32 staging st[128][129] aliases stage 0; aux @196608
#define SM_AH 0
#define SM_AL 16384
#define SM_BH 32768
#define SM_BL 49152
#define STG   65536
#define NSTG  3
#define SM_AUX 196608
#define SMEM_SZ 197632

__device__ __forceinline__ uint32_t smem_u32(const void* p) {
    uint32_t a;
    asm("{ .reg .u64 t; cvta.to.shared.u64 t, %1; cvt.u32.u64 %0, t; }" : "=r"(a) : "l"(p));
    return a;
}
#define SW128(o) ((o) ^ (((o) >> 3) & 0x70))

__device__ __forceinline__ void cpa16(uint32_t dst, const void* src) {
    asm volatile("cp.async.cg.shared.global [%0], [%1], 16;" :: "r"(dst), "l"(src));
}
__device__ __forceinline__ void cpa16z(uint32_t dst, const void* src, bool v) {
    int sz = v ? 16 : 0;
    asm volatile("cp.async.cg.shared.global [%0], [%1], 16, %2;" :: "r"(dst), "l"(src), "r"(sz));
}
#define CP_COMMIT() asm volatile("cp.async.commit_group;" ::: "memory")
#define CP_WAIT1()  asm volatile("cp.async.wait_group 1;" ::: "memory")
#define CP_WAIT0()  asm volatile("cp.async.wait_group 0;" ::: "memory")

__device__ __forceinline__ void ldm4(uint32_t r[4], uint32_t addr) {
    asm volatile("ldmatrix.sync.aligned.m8n8.x4.shared.b16 {%0,%1,%2,%3}, [%4];"
        : "=r"(r[0]), "=r"(r[1]), "=r"(r[2]), "=r"(r[3]) : "r"(addr));
}
__device__ __forceinline__ void mma_bf16(float d[4], const uint32_t a[4],
                                         uint32_t b0, uint32_t b1) {
    asm volatile("mma.sync.aligned.m16n8k16.row.col.f32.bf16.bf16.f32 "
        "{%0,%1,%2,%3}, {%4,%5,%6,%7}, {%8,%9}, {%0,%1,%2,%3};"
        : "+f"(d[0]), "+f"(d[1]), "+f"(d[2]), "+f"(d[3])
        : "r"(a[0]), "r"(a[1]), "r"(a[2]), "r"(a[3]), "r"(b0), "r"(b1));
}

// 3-term split-bf16 K=64 chunk on one warp tile (32m x 32n):
// acc += Ah*Bh + Ah*Bl + Al*Bh
__device__ __forceinline__ void warp_chunk3(float acc[2][4][4],
    uint32_t sAh, uint32_t sAl, uint32_t sBh, uint32_t sBl,
    int wm, int wn, int lane)
{
    const int tile = lane >> 3, tr = lane & 7;
    #pragma unroll
    for (int kk = 0; kk < 4; kk++) {
        uint32_t ah[2][4], al[2][4];
        #pragma unroll
        for (int mf = 0; mf < 2; mf++) {
            int row = wm + mf * 16 + ((tile & 1) << 3) + tr;
            int g   = 2 * kk + (tile >> 1);
            uint32_t off = SW128((uint32_t)(row * 128 + g * 16));
            ldm4(ah[mf], sAh + off);
            ldm4(al[mf], sAl + off);
        }
        #pragma unroll
        for (int nf = 0; nf < 4; nf += 2) {
            int row = wn + nf * 8 + ((tile >> 1) << 3) + tr;
            int g   = 2 * kk + (tile & 1);
            uint32_t off = SW128((uint32_t)(row * 128 + g * 16));
            uint32_t bh[4], bl[4];
            ldm4(bh, sBh + off);
            ldm4(bl, sBl + off);
            #pragma unroll
            for (int mf = 0; mf < 2; mf++) {
                mma_bf16(acc[mf][nf],     ah[mf], bh[0], bh[1]);
                mma_bf16(acc[mf][nf],     ah[mf], bl[0], bl[1]);
                mma_bf16(acc[mf][nf],     al[mf], bh[0], bh[1]);
                mma_bf16(acc[mf][nf + 1], ah[mf], bh[2], bh[3]);
                mma_bf16(acc[mf][nf + 1], ah[mf], bl[2], bl[3]);
                mma_bf16(acc[mf][nf + 1], al[mf], bh[2], bh[3]);
            }
        }
    }
}

// accumulators -> fp32 staging st[m*129+n]
__device__ __forceinline__ void acc_to_staging(float* st, float acc[2][4][4],
                                               int wm, int wn, int lane, bool relu) {
    const int r0 = lane >> 2, c0 = (lane & 3) * 2;
    #pragma unroll
    for (int mf = 0; mf < 2; mf++)
        #pragma unroll
        for (int nf = 0; nf < 4; nf++)
            #pragma unroll
            for (int i = 0; i < 4; i++) {
                int m = wm + mf * 16 + r0 + (i >> 1) * 8;
                int n = wn + nf * 8 + c0 + (i & 1);
                float v = acc[mf][nf][i];
                st[m * 129 + n] = relu ? fmaxf(v, 0.0f) : v;
            }
}

// async 128x64 bf16 K-major tile fill (swizzled), rstride in elements, NT=512
__device__ __forceinline__ void fill64_async(uint32_t dst, const __nv_bfloat16* src, int rstride) {
    int t = threadIdx.x;
    #pragma unroll
    for (int i = 0; i < 2; i++) {
        int idx = t + i * NT, r = idx >> 3, ch = idx & 7;
        cpa16(dst + SW128((uint32_t)(r * 128 + ch * 16)),
              src + (size_t)r * rstride + ch * 8);
    }
}

__device__ __forceinline__ void split_store(float v, __nv_bfloat16* ph, __nv_bfloat16* pl, size_t o) {
    __nv_bfloat16 h = __float2bfloat16(v);
    ph[o] = h;
    pl[o] = __float2bfloat16(v - __bfloat162float(h));
}

__device__ __forceinline__ float fast_exp(float x) {
    x = fmaxf(x, -87.0f);
    float y  = x * 1.4426950408889634f;
    float fl = floorf(y);
    float t  = (y - fl) * 0.6931471805599453f;
    float p = 1.3888889e-3f;
    p = fmaf(p, t, 8.3333333e-3f);
    p = fmaf(p, t, 4.1666667e-2f);
    p = fmaf(p, t, 1.6666667e-1f);
    p = fmaf(p, t, 0.5f);
    p = fmaf(p, t, 1.0f);
    p = fmaf(p, t, 1.0f);
    return __int_as_float(((int)fl + 127) << 23) * p;
}

// ---------------- prep: weights -> [w][s][co][ci] hi/lo --------------------
__global__ __launch_bounds__(256) void prep_w_kernel(
    const float* __restrict__ w1, const float* __restrict__ w2)
{
    int idx = blockIdx.x * 256 + threadIdx.x;        // < 1179648
    int w = idx / 589824, r = idx - w * 589824;
    int s = r >> 16, r2 = r & 65535, co = r2 >> 8, ci = r2 & 255;
    const float* wp = w ? w2 : w1;
    split_store(wp[co * 2304 + ci * 9 + s], g_wh, g_wl, (size_t)idx);
}

// ---------------- prep: ref [b][c][pos] -> refT [b][pos][ci] hi/lo ---------
__global__ void prep_refT_kernel(const float* __restrict__ ref)
{
    __shared__ float tile[32][33];
    int b = blockIdx.z, p0 = blockIdx.x * 32, c0 = blockIdx.y * 32;
    int x = threadIdx.x, y = threadIdx.y;            // (32, 8)
    #pragma unroll
    for (int i = 0; i < 4; i++)
        tile[y + i * 8][x] = ref[((size_t)(b * 256 + c0 + y + i * 8)) * 4096 + p0 + x];
    __syncthreads();
    #pragma unroll
    for (int i = 0; i < 4; i++) {
        int p = y + i * 8;
        split_store(tile[x][p], g_refTh, g_refTl,
                    ((size_t)((b << 12) + p0 + p)) * 256 + c0 + x);
    }
}

// ---------------- conv 3x3 SAME + relu, 3-stage pipelined mma.sync ---------
// grid (32 pos-tiles, 4 = w*2+half, B_). D[co 128][pos 128]. 36 K-chunks.
__global__ __launch_bounds__(NT) void conv_mma_kernel()
{
    extern __shared__ char sm[];
    const uint32_t sb = smem_u32(sm);
    const int t = threadIdx.x, lane = t & 31, wid = t >> 5;
    const int wm = (wid & 3) * 32, wn = (wid >> 2) * 32;
    const int pos0 = blockIdx.x * 128;
    const int w = blockIdx.y >> 1, half = blockIdx.y & 1;
    const int b = blockIdx.z;
    float acc[2][4][4] = {};

    auto do_fill = [&](int kc, int stg) {
        int s = kc >> 2, cc = kc & 3, ci0 = cc * 64;
        int dy = s / 3 - 1, dx = s % 3 - 1, shift = dy * 64 + dx;
        uint32_t base = sb + stg * STG;
        const size_t wbase = ((size_t)((w * 9 + s) * 256 + half * 128)) * 256 + ci0;
        #pragma unroll
        for (int i = 0; i < 2; i++) {
            int idx = t + i * NT, r = idx >> 3, ch = idx & 7;
            uint32_t sw = SW128((uint32_t)(r * 128 + ch * 16));
            cpa16(base + SM_AH + sw, g_wh + wbase + (size_t)r * 256 + ch * 8);
            cpa16(base + SM_AL + sw, g_wl + wbase + (size_t)r * 256 + ch * 8);
        }
        #pragma unroll
        for (int i = 0; i < 2; i++) {
            int idx = t + i * NT, r = idx >> 3, ch = idx & 7;
            int pos = pos0 + r, y = pos >> 6, x = pos & 63;
            int yy = y + dy, xx = x + dx;
            bool valid = ((unsigned)yy < 64u) && ((unsigned)xx < 64u);
            long long so = valid ?
                ((long long)((b << 12) + pos + shift)) * 256 + ci0 + ch * 8 : 0;
            uint32_t sw = SW128((uint32_t)(r * 128 + ch * 16));
            cpa16z(base + SM_BH + sw, g_refTh + so, valid);
            cpa16z(base + SM_BL + sw, g_refTl + so, valid);
        }
    };

    do_fill(0, 0); CP_COMMIT();
    do_fill(1, 1); CP_COMMIT();
    for (int kc = 0; kc < 36; kc++) {
        int cur = kc % NSTG;
        if (kc + 1 < 36) CP_WAIT1(); else CP_WAIT0();
        __syncthreads();
        if (kc + 2 < 36) { do_fill(kc + 2, (kc + 2) % NSTG); CP_COMMIT(); }
        uint32_t base = sb + cur * STG;
        warp_chunk3(acc, base + SM_AH, base + SM_AL, base + SM_BH, base + SM_BL, wm, wn, lane);
    }
    __syncthreads();

    // epilogue: relu + split, write x1t (w=0) or V (w=1)
    float* st = (float*)sm;
    acc_to_staging(st, acc, wm, wn, lane, true);
    __syncthreads();
    if (w == 0) {
        for (int i = t; i < 16384; i += NT) {
            int p = i >> 7, c = i & 127;      // coalesced over c
            split_store(st[c * 129 + p], g_x1th, g_x1tl,
                        ((size_t)((b << 12) + pos0 + p)) * 256 + half * 128 + c);
        }
    } else {
        for (int i = t; i < 16384; i += NT) {
            int c = i >> 7, p = i & 127;      // coalesced over p
            split_store(st[c * 129 + p], g_Vh, g_Vl,
                        ((size_t)((b << 8) + half * 128 + c)) * 4096 + pos0 + p);
        }
    }
}

// ---------------- scores = x1t . x1t^T (symmetric, triangular grid) --------
__global__ __launch_bounds__(NT) void scores_mma_kernel()
{
    extern __shared__ char sm[];
    const uint32_t sb = smem_u32(sm);
    const int t = threadIdx.x, lane = t & 31, wid = t >> 5;
    const int wm = (wid & 3) * 32, wn = (wid >> 2) * 32;
    const int b = blockIdx.y;
    int i = 0, pp = blockIdx.x;
    while (pp >= 32 - i) { pp -= 32 - i; i++; }
    const int n0 = i * 128, m0 = (i + pp) * 128;
    float acc[2][4][4] = {};

    auto do_fill = [&](int kc, int stg) {
        int k0 = kc * 64;
        uint32_t base = sb + stg * STG;
        fill64_async(base + SM_AH, g_x1th + ((size_t)((b << 12) + n0)) * 256 + k0, 256);
        fill64_async(base + SM_AL, g_x1tl + ((size_t)((b << 12) + n0)) * 256 + k0, 256);
        fill64_async(base + SM_BH, g_x1th + ((size_t)((b << 12) + m0)) * 256 + k0, 256);
        fill64_async(base + SM_BL, g_x1tl + ((size_t)((b << 12) + m0)) * 256 + k0, 256);
    };

    do_fill(0, 0); CP_COMMIT();
    do_fill(1, 1); CP_COMMIT();
    for (int kc = 0; kc < 4; kc++) {
        int cur = kc % NSTG;
        if (kc + 1 < 4) CP_WAIT1(); else CP_WAIT0();
        __syncthreads();
        if (kc + 2 < 4) { do_fill(kc + 2, (kc + 2) % NSTG); CP_COMMIT(); }
        uint32_t base = sb + cur * STG;
        warp_chunk3(acc, base + SM_AH, base + SM_AL, base + SM_BH, base + SM_BL, wm, wn, lane);
    }
    __syncthreads();

    float* st = (float*)sm;
    acc_to_staging(st, acc, wm, wn, lane, false);
    __syncthreads();
    float* Sb = g_S + (size_t)b * HW_ * HW_;
    for (int ii = t; ii < 16384; ii += NT) {
        int r = ii >> 7, c = ii & 127;
        Sb[(size_t)(n0 + r) * 4096 + m0 + c] = st[r * 129 + c];
    }
    if (n0 != m0) {
        for (int ii = t; ii < 16384; ii += NT) {
            int r = ii >> 7, c = ii & 127;
            Sb[(size_t)(m0 + r) * 4096 + n0 + c] = st[c * 129 + r];
        }
    }
}

// ---------------- row stats + E materialization (bf16 hi/lo) ---------------
// By symmetry row stats == column stats. E[m][n] = exp(S[m][n] - mx[m]).
__global__ __launch_bounds__(256) void rowstats_kernel()
{
    __shared__ float red[256];
    const int b = blockIdx.y, m = blockIdx.x, t = threadIdx.x;
    const float* __restrict__ row = g_S + ((size_t)b * HW_ + m) * HW_;
    float4 v[4];
    #pragma unroll
    for (int i = 0; i < 4; i++) v[i] = *(const float4*)(row + i * 1024 + t * 4);
    float mx = -1e30f;
    #pragma unroll
    for (int i = 0; i < 4; i++)
        mx = fmaxf(mx, fmaxf(fmaxf(v[i].x, v[i].y), fmaxf(v[i].z, v[i].w)));
    red[t] = mx;
    __syncthreads();
    #pragma unroll
    for (int s = 128; s >= 32; s >>= 1) {
        if (t < s) red[t] = fmaxf(red[t], red[t + s]);
        __syncthreads();
    }
    if (t < 32) {
        float r = red[t];
        #pragma unroll
        for (int o = 16; o > 0; o >>= 1) r = fmaxf(r, __shfl_xor_sync(~0u, r, o));
        red[0] = r;
    }
    __syncthreads();
    mx = red[0];
    __syncthreads();
    float sum = 0.0f;
    #pragma unroll
    for (int i = 0; i < 4; i++) {
        float vv[4] = {v[i].x, v[i].y, v[i].z, v[i].w};
        __nv_bfloat16 hh[4], ll[4];
        #pragma unroll
        for (int j = 0; j < 4; j++) {
            float e = fast_exp(vv[j] - mx);
            sum += e;
            __nv_bfloat16 h = __float2bfloat16(e);
            hh[j] = h;
            ll[j] = __float2bfloat16(e - __bfloat162float(h));
        }
        size_t eo = ((size_t)((b << 12) + m)) * 4096 + i * 1024 + t * 4;
        *(uint2*)(g_Eh + eo) = *(uint2*)hh;
        *(uint2*)(g_El + eo) = *(uint2*)ll;
    }
    red[t] = sum;
    __syncthreads();
    #pragma unroll
    for (int s = 128; s >= 32; s >>= 1) {
        if (t < s) red[t] += red[t + s];
        __syncthreads();
    }
    if (t < 32) {
        float r = red[t];
        #pragma unroll
        for (int o = 16; o > 0; o >>= 1) r += __shfl_xor_sync(~0u, r, o);
        if (t == 0) g_rcp[b * HW_ + m] = 1.0f / r;
    }
}

// ---------------- AV: out = gamma * rcp[m] * (V . E^T) + ref ---------------
// grid (32 m-tiles, 2 c-halves, B_). Pure pipelined GEMM, K = n (4096).
__global__ __launch_bounds__(NT) void av_mma_kernel(
    const float* __restrict__ ref, const float* __restrict__ gamma_p,
    float* __restrict__ out)
{
    extern __shared__ char sm[];
    const uint32_t sb = smem_u32(sm);
    const int t = threadIdx.x, lane = t & 31, wid = t >> 5;
    const int wm = (wid & 3) * 32, wn = (wid >> 2) * 32;
    const int m0 = blockIdx.x * 128, chalf = blockIdx.y, b = blockIdx.z;
    float acc[2][4][4] = {};

    auto do_fill = [&](int kc, int stg) {
        int k0 = kc * 64;
        uint32_t base = sb + stg * STG;
        const size_t vbase = ((size_t)((b << 8) + chalf * 128)) * 4096 + k0;
        const size_t ebase = ((size_t)((b << 12) + m0)) * 4096 + k0;
        fill64_async(base + SM_AH, g_Vh + vbase, 4096);
        fill64_async(base + SM_AL, g_Vl + vbase, 4096);
        fill64_async(base + SM_BH, g_Eh + ebase, 4096);
        fill64_async(base + SM_BL, g_El + ebase, 4096);
    };

    do_fill(0, 0); CP_COMMIT();
    do_fill(1, 1); CP_COMMIT();
    for (int kc = 0; kc < 64; kc++) {
        int cur = kc % NSTG;
        if (kc + 1 < 64) CP_WAIT1(); else CP_WAIT0();
        __syncthreads();
        if (kc + 2 < 64) { do_fill(kc + 2, (kc + 2) % NSTG); CP_COMMIT(); }
        uint32_t base = sb + cur * STG;
        warp_chunk3(acc, base + SM_AH, base + SM_AL, base + SM_BH, base + SM_BL, wm, wn, lane);
    }
    __syncthreads();

    // epilogue
    float* st = (float*)sm;
    acc_to_staging(st, acc, wm, wn, lane, false);
    float* s_rc = (float*)(sm + SM_AUX);
    if (t < 128) s_rc[t] = (*gamma_p) * g_rcp[(b << 12) + m0 + t];
    __syncthreads();
    for (int ii = t; ii < 16384; ii += NT) {
        int cl = ii >> 7, n = ii & 127;       // coalesced over n
        size_t o = ((size_t)((b << 8) + chalf * 128 + cl)) * 4096 + m0 + n;
        out[o] = fmaf(st[cl * 129 + n], s_rc[n], ref[o]);
    }
}

// ---------------------------------------------------------------------------
extern "C" void kernel_launch(void* const* d_in, const int* in_sizes, int n_in,
                              void* d_out, int out_size)
{
    const float* ref   = (const float*)d_in[1];   // d_in[0] 'inputs' is dead in reference
    const float* w1    = (const float*)d_in[2];
    const float* w2    = (const float*)d_in[3];
    const float* gamma = (const float*)d_in[4];
    float* out = (float*)d_out;

    cudaFuncSetAttribute(conv_mma_kernel,   cudaFuncAttributeMaxDynamicSharedMemorySize, SMEM_SZ);
    cudaFuncSetAttribute(scores_mma_kernel, cudaFuncAttributeMaxDynamicSharedMemorySize, SMEM_SZ);
    cudaFuncSetAttribute(av_mma_kernel,     cudaFuncAttributeMaxDynamicSharedMemorySize, SMEM_SZ);

    prep_w_kernel<<<4608, 256>>>(w1, w2);
    prep_refT_kernel<<<dim3(128, 8, B_), dim3(32, 8)>>>(ref);
    conv_mma_kernel<<<dim3(32, 4, B_), NT, SMEM_SZ>>>();
    scores_mma_kernel<<<dim3(528, B_), NT, SMEM_SZ>>>();
    rowstats_kernel<<<dim3(4096, B_), 256>>>();
    av_mma_kernel<<<dim3(32, 2, B_), NT, SMEM_SZ>>>(ref, gamma, out);
}

// round 10
// speedup vs baseline: 1.9039x; 1.9039x over previous
#include <cuda_runtime.h>
#include <cuda_fp16.h>
#include <cstdint>

#define HW_  4096
#define C_   256
#define B_   4
#define NT   512

// ---------------- scratch (__device__ globals per allocation rules) --------
__device__ __align__(1024) __half g_refT[B_ * HW_ * C_];  // [b*4096+pos][ci]
__device__ __align__(1024) __half g_w[2 * 9 * C_ * C_];   // [w][s][co][ci]
__device__ __align__(1024) __half g_x1t[B_ * HW_ * C_];   // [b*4096+pos][c]
__device__ __align__(1024) __half g_V[B_ * C_ * HW_];     // [b][c][pos]
__device__ __align__(1024) __half g_E[(size_t)B_ * HW_ * HW_]; // exp(S-mx) [m][n]
__device__ float g_S[(size_t)B_ * HW_ * HW_];
__device__ float g_rcp[B_ * HW_];

// ---------------- smem: 4 pipeline stages + aux ----------------------------
// stage s at s*32768: A +0, B +16K (each 128 rows x 128B, SW128)
// epilogue fp32 staging st[128][129] aliases stages; aux @131072
#define SM_A  0
#define SM_B  16384
#define STG   32768
#define NSTG  4
#define SM_AUX 131072
#define SMEM_SZ 132096

__device__ __forceinline__ uint32_t smem_u32(const void* p) {
    uint32_t a;
    asm("{ .reg .u64 t; cvta.to.shared.u64 t, %1; cvt.u32.u64 %0, t; }" : "=r"(a) : "l"(p));
    return a;
}
#define SW128(o) ((o) ^ (((o) >> 3) & 0x70))

__device__ __forceinline__ void cpa16(uint32_t dst, const void* src) {
    asm volatile("cp.async.cg.shared.global [%0], [%1], 16;" :: "r"(dst), "l"(src));
}
__device__ __forceinline__ void cpa16z(uint32_t dst, const void* src, bool v) {
    int sz = v ? 16 : 0;
    asm volatile("cp.async.cg.shared.global [%0], [%1], 16, %2;" :: "r"(dst), "l"(src), "r"(sz));
}
#define CP_COMMIT() asm volatile("cp.async.commit_group;" ::: "memory")
#define CP_WAIT2()  asm volatile("cp.async.wait_group 2;" ::: "memory")
#define CP_WAIT0()  asm volatile("cp.async.wait_group 0;" ::: "memory")

__device__ __forceinline__ void ldm4(uint32_t r[4], uint32_t addr) {
    asm volatile("ldmatrix.sync.aligned.m8n8.x4.shared.b16 {%0,%1,%2,%3}, [%4];"
        : "=r"(r[0]), "=r"(r[1]), "=r"(r[2]), "=r"(r[3]) : "r"(addr));
}
__device__ __forceinline__ void mma_f16(float d[4], const uint32_t a[4],
                                        uint32_t b0, uint32_t b1) {
    asm volatile("mma.sync.aligned.m16n8k16.row.col.f32.f16.f16.f32 "
        "{%0,%1,%2,%3}, {%4,%5,%6,%7}, {%8,%9}, {%0,%1,%2,%3};"
        : "+f"(d[0]), "+f"(d[1]), "+f"(d[2]), "+f"(d[3])
        : "r"(a[0]), "r"(a[1]), "r"(a[2]), "r"(a[3]), "r"(b0), "r"(b1));
}

// single-term fp16 K=64 chunk on one warp tile (32m x 32n)
__device__ __forceinline__ void warp_chunk1(float acc[2][4][4],
    uint32_t sA, uint32_t sB, int wm, int wn, int lane)
{
    const int tile = lane >> 3, tr = lane & 7;
    #pragma unroll
    for (int kk = 0; kk < 4; kk++) {
        uint32_t a[2][4];
        #pragma unroll
        for (int mf = 0; mf < 2; mf++) {
            int row = wm + mf * 16 + ((tile & 1) << 3) + tr;
            int g   = 2 * kk + (tile >> 1);
            ldm4(a[mf], sA + SW128((uint32_t)(row * 128 + g * 16)));
        }
        #pragma unroll
        for (int nf = 0; nf < 4; nf += 2) {
            int row = wn + nf * 8 + ((tile >> 1) << 3) + tr;
            int g   = 2 * kk + (tile & 1);
            uint32_t b[4];
            ldm4(b, sB + SW128((uint32_t)(row * 128 + g * 16)));
            #pragma unroll
            for (int mf = 0; mf < 2; mf++) {
                mma_f16(acc[mf][nf],     a[mf], b[0], b[1]);
                mma_f16(acc[mf][nf + 1], a[mf], b[2], b[3]);
            }
        }
    }
}

// accumulators -> fp32 staging st[m*129+n]
__device__ __forceinline__ void acc_to_staging(float* st, float acc[2][4][4],
                                               int wm, int wn, int lane, bool relu) {
    const int r0 = lane >> 2, c0 = (lane & 3) * 2;
    #pragma unroll
    for (int mf = 0; mf < 2; mf++)
        #pragma unroll
        for (int nf = 0; nf < 4; nf++)
            #pragma unroll
            for (int i = 0; i < 4; i++) {
                int m = wm + mf * 16 + r0 + (i >> 1) * 8;
                int n = wn + nf * 8 + c0 + (i & 1);
                float v = acc[mf][nf][i];
                st[m * 129 + n] = relu ? fmaxf(v, 0.0f) : v;
            }
}

// async 128x64 fp16 K-major tile fill (swizzled), rstride in elements, NT=512
__device__ __forceinline__ void fill64_async(uint32_t dst, const __half* src, int rstride) {
    int t = threadIdx.x;
    #pragma unroll
    for (int i = 0; i < 2; i++) {
        int idx = t + i * NT, r = idx >> 3, ch = idx & 7;
        cpa16(dst + SW128((uint32_t)(r * 128 + ch * 16)),
              src + (size_t)r * rstride + ch * 8);
    }
}

__device__ __forceinline__ float fast_exp(float x) {
    x = fmaxf(x, -87.0f);
    float y  = x * 1.4426950408889634f;
    float fl = floorf(y);
    float t  = (y - fl) * 0.6931471805599453f;
    float p = 1.3888889e-3f;
    p = fmaf(p, t, 8.3333333e-3f);
    p = fmaf(p, t, 4.1666667e-2f);
    p = fmaf(p, t, 1.6666667e-1f);
    p = fmaf(p, t, 0.5f);
    p = fmaf(p, t, 1.0f);
    p = fmaf(p, t, 1.0f);
    return __int_as_float(((int)fl + 127) << 23) * p;
}

// ---------------- prep: weights -> [w][s][co][ci] fp16 ---------------------
__global__ __launch_bounds__(256) void prep_w_kernel(
    const float* __restrict__ w1, const float* __restrict__ w2)
{
    int idx = blockIdx.x * 256 + threadIdx.x;        // < 1179648
    int w = idx / 589824, r = idx - w * 589824;
    int s = r >> 16, r2 = r & 65535, co = r2 >> 8, ci = r2 & 255;
    const float* wp = w ? w2 : w1;
    g_w[idx] = __float2half_rn(wp[co * 2304 + ci * 9 + s]);
}

// ---------------- prep: ref [b][c][pos] -> refT [b][pos][ci] fp16 ----------
__global__ void prep_refT_kernel(const float* __restrict__ ref)
{
    __shared__ float tile[32][33];
    int b = blockIdx.z, p0 = blockIdx.x * 32, c0 = blockIdx.y * 32;
    int x = threadIdx.x, y = threadIdx.y;            // (32, 8)
    #pragma unroll
    for (int i = 0; i < 4; i++)
        tile[y + i * 8][x] = ref[((size_t)(b * 256 + c0 + y + i * 8)) * 4096 + p0 + x];
    __syncthreads();
    #pragma unroll
    for (int i = 0; i < 4; i++) {
        int p = y + i * 8;
        g_refT[((size_t)((b << 12) + p0 + p)) * 256 + c0 + x] =
            __float2half_rn(tile[x][p]);
    }
}

// ---------------- conv 3x3 SAME + relu, 4-stage pipelined mma.sync ---------
// grid (32 pos-tiles, 4 = w*2+half, B_). D[co 128][pos 128]. 36 K-chunks.
__global__ __launch_bounds__(NT) void conv_mma_kernel()
{
    extern __shared__ char sm[];
    const uint32_t sb = smem_u32(sm);
    const int t = threadIdx.x, lane = t & 31, wid = t >> 5;
    const int wm = (wid & 3) * 32, wn = (wid >> 2) * 32;
    const int pos0 = blockIdx.x * 128;
    const int w = blockIdx.y >> 1, half = blockIdx.y & 1;
    const int b = blockIdx.z;
    float acc[2][4][4] = {};

    auto do_fill = [&](int kc, int stg) {
        int s = kc >> 2, cc = kc & 3, ci0 = cc * 64;
        int dy = s / 3 - 1, dx = s % 3 - 1, shift = dy * 64 + dx;
        uint32_t base = sb + stg * STG;
        const size_t wbase = ((size_t)((w * 9 + s) * 256 + half * 128)) * 256 + ci0;
        #pragma unroll
        for (int i = 0; i < 2; i++) {
            int idx = t + i * NT, r = idx >> 3, ch = idx & 7;
            cpa16(base + SM_A + SW128((uint32_t)(r * 128 + ch * 16)),
                  g_w + wbase + (size_t)r * 256 + ch * 8);
        }
        #pragma unroll
        for (int i = 0; i < 2; i++) {
            int idx = t + i * NT, r = idx >> 3, ch = idx & 7;
            int pos = pos0 + r, y = pos >> 6, x = pos & 63;
            int yy = y + dy, xx = x + dx;
            bool valid = ((unsigned)yy < 64u) && ((unsigned)xx < 64u);
            long long so = valid ?
                ((long long)((b << 12) + pos + shift)) * 256 + ci0 + ch * 8 : 0;
            cpa16z(base + SM_B + SW128((uint32_t)(r * 128 + ch * 16)), g_refT + so, valid);
        }
    };

    do_fill(0, 0); CP_COMMIT();
    do_fill(1, 1); CP_COMMIT();
    do_fill(2, 2); CP_COMMIT();
    for (int kc = 0; kc < 36; kc++) {
        CP_WAIT2();
        __syncthreads();
        if (kc + 3 < 36) do_fill(kc + 3, (kc + 3) % NSTG);
        CP_COMMIT();
        uint32_t base = sb + (kc % NSTG) * STG;
        warp_chunk1(acc, base + SM_A, base + SM_B, wm, wn, lane);
    }
    CP_WAIT0();
    __syncthreads();

    // epilogue: relu, write x1t (w=0) or V (w=1) as fp16
    float* st = (float*)sm;
    acc_to_staging(st, acc, wm, wn, lane, true);
    __syncthreads();
    if (w == 0) {
        for (int i = t; i < 16384; i += NT) {
            int p = i >> 7, c = i & 127;      // coalesced over c
            g_x1t[((size_t)((b << 12) + pos0 + p)) * 256 + half * 128 + c] =
                __float2half_rn(st[c * 129 + p]);
        }
    } else {
        for (int i = t; i < 16384; i += NT) {
            int c = i >> 7, p = i & 127;      // coalesced over p
            g_V[((size_t)((b << 8) + half * 128 + c)) * 4096 + pos0 + p] =
                __float2half_rn(st[c * 129 + p]);
        }
    }
}

// ---------------- scores = x1t . x1t^T (symmetric, triangular grid) --------
__global__ __launch_bounds__(NT) void scores_mma_kernel()
{
    extern __shared__ char sm[];
    const uint32_t sb = smem_u32(sm);
    const int t = threadIdx.x, lane = t & 31, wid = t >> 5;
    const int wm = (wid & 3) * 32, wn = (wid >> 2) * 32;
    const int b = blockIdx.y;
    int i = 0, pp = blockIdx.x;
    while (pp >= 32 - i) { pp -= 32 - i; i++; }
    const int n0 = i * 128, m0 = (i + pp) * 128;
    float acc[2][4][4] = {};

    auto do_fill = [&](int kc, int stg) {
        int k0 = kc * 64;
        uint32_t base = sb + stg * STG;
        fill64_async(base + SM_A, g_x1t + ((size_t)((b << 12) + n0)) * 256 + k0, 256);
        fill64_async(base + SM_B, g_x1t + ((size_t)((b << 12) + m0)) * 256 + k0, 256);
    };

    do_fill(0, 0); CP_COMMIT();
    do_fill(1, 1); CP_COMMIT();
    do_fill(2, 2); CP_COMMIT();
    for (int kc = 0; kc < 4; kc++) {
        CP_WAIT2();
        __syncthreads();
        if (kc + 3 < 4) do_fill(kc + 3, (kc + 3) % NSTG);
        CP_COMMIT();
        uint32_t base = sb + (kc % NSTG) * STG;
        warp_chunk1(acc, base + SM_A, base + SM_B, wm, wn, lane);
    }
    CP_WAIT0();
    __syncthreads();

    float* st = (float*)sm;
    acc_to_staging(st, acc, wm, wn, lane, false);
    __syncthreads();
    float* Sb = g_S + (size_t)b * HW_ * HW_;
    for (int ii = t; ii < 16384; ii += NT) {
        int r = ii >> 7, c = ii & 127;
        Sb[(size_t)(n0 + r) * 4096 + m0 + c] = st[r * 129 + c];
    }
    if (n0 != m0) {
        for (int ii = t; ii < 16384; ii += NT) {
            int r = ii >> 7, c = ii & 127;
            Sb[(size_t)(m0 + r) * 4096 + n0 + c] = st[c * 129 + r];
        }
    }
}

// ---------------- row stats + E materialization (fp16) ---------------------
// By symmetry row stats == column stats. E[m][n] = exp(S[m][n] - mx[m]).
__global__ __launch_bounds__(256) void rowstats_kernel()
{
    __shared__ float red[256];
    const int b = blockIdx.y, m = blockIdx.x, t = threadIdx.x;
    const float* __restrict__ row = g_S + ((size_t)b * HW_ + m) * HW_;
    float4 v[4];
    #pragma unroll
    for (int i = 0; i < 4; i++) v[i] = *(const float4*)(row + i * 1024 + t * 4);
    float mx = -1e30f;
    #pragma unroll
    for (int i = 0; i < 4; i++)
        mx = fmaxf(mx, fmaxf(fmaxf(v[i].x, v[i].y), fmaxf(v[i].z, v[i].w)));
    red[t] = mx;
    __syncthreads();
    #pragma unroll
    for (int s = 128; s >= 32; s >>= 1) {
        if (t < s) red[t] = fmaxf(red[t], red[t + s]);
        __syncthreads();
    }
    if (t < 32) {
        float r = red[t];
        #pragma unroll
        for (int o = 16; o > 0; o >>= 1) r = fmaxf(r, __shfl_xor_sync(~0u, r, o));
        red[0] = r;
    }
    __syncthreads();
    mx = red[0];
    __syncthreads();
    float sum = 0.0f;
    #pragma unroll
    for (int i = 0; i < 4; i++) {
        float vv[4] = {v[i].x, v[i].y, v[i].z, v[i].w};
        __half hh[4];
        #pragma unroll
        for (int j = 0; j < 4; j++) {
            float e = fast_exp(vv[j] - mx);
            sum += e;
            hh[j] = __float2half_rn(e);
        }
        size_t eo = ((size_t)((b << 12) + m)) * 4096 + i * 1024 + t * 4;
        *(uint2*)(g_E + eo) = *(uint2*)hh;
    }
    red[t] = sum;
    __syncthreads();
    #pragma unroll
    for (int s = 128; s >= 32; s >>= 1) {
        if (t < s) red[t] += red[t + s];
        __syncthreads();
    }
    if (t < 32) {
        float r = red[t];
        #pragma unroll
        for (int o = 16; o > 0; o >>= 1) r += __shfl_xor_sync(~0u, r, o);
        if (t == 0) g_rcp[b * HW_ + m] = 1.0f / r;
    }
}

// ---------------- AV: out = gamma * rcp[m] * (V . E^T) + ref ---------------
// grid (32 m-tiles, 2 c-halves, B_). Pure pipelined GEMM, K = n (4096).
__global__ __launch_bounds__(NT) void av_mma_kernel(
    const float* __restrict__ ref, const float* __restrict__ gamma_p,
    float* __restrict__ out)
{
    extern __shared__ char sm[];
    const uint32_t sb = smem_u32(sm);
    const int t = threadIdx.x, lane = t & 31, wid = t >> 5;
    const int wm = (wid & 3) * 32, wn = (wid >> 2) * 32;
    const int m0 = blockIdx.x * 128, chalf = blockIdx.y, b = blockIdx.z;
    float acc[2][4][4] = {};

    auto do_fill = [&](int kc, int stg) {
        int k0 = kc * 64;
        uint32_t base = sb + stg * STG;
        fill64_async(base + SM_A,
                     g_V + ((size_t)((b << 8) + chalf * 128)) * 4096 + k0, 4096);
        fill64_async(base + SM_B,
                     g_E + ((size_t)((b << 12) + m0)) * 4096 + k0, 4096);
    };

    do_fill(0, 0); CP_COMMIT();
    do_fill(1, 1); CP_COMMIT();
    do_fill(2, 2); CP_COMMIT();
    for (int kc = 0; kc < 64; kc++) {
        CP_WAIT2();
        __syncthreads();
        if (kc + 3 < 64) do_fill(kc + 3, (kc + 3) % NSTG);
        CP_COMMIT();
        uint32_t base = sb + (kc % NSTG) * STG;
        warp_chunk1(acc, base + SM_A, base + SM_B, wm, wn, lane);
    }
    CP_WAIT0();
    __syncthreads();

    // epilogue
    float* st = (float*)sm;
    acc_to_staging(st, acc, wm, wn, lane, false);
    float* s_rc = (float*)(sm + SM_AUX);
    if (t < 128) s_rc[t] = (*gamma_p) * g_rcp[(b << 12) + m0 + t];
    __syncthreads();
    for (int ii = t; ii < 16384; ii += NT) {
        int cl = ii >> 7, n = ii & 127;       // coalesced over n
        size_t o = ((size_t)((b << 8) + chalf * 128 + cl)) * 4096 + m0 + n;
        out[o] = fmaf(st[cl * 129 + n], s_rc[n], ref[o]);
    }
}

// ---------------------------------------------------------------------------
extern "C" void kernel_launch(void* const* d_in, const int* in_sizes, int n_in,
                              void* d_out, int out_size)
{
    const float* ref   = (const float*)d_in[1];   // d_in[0] 'inputs' is dead in reference
    const float* w1    = (const float*)d_in[2];
    const float* w2    = (const float*)d_in[3];
    const float* gamma = (const float*)d_in[4];
    float* out = (float*)d_out;

    cudaFuncSetAttribute(conv_mma_kernel,   cudaFuncAttributeMaxDynamicSharedMemorySize, SMEM_SZ);
    cudaFuncSetAttribute(scores_mma_kernel, cudaFuncAttributeMaxDynamicSharedMemorySize, SMEM_SZ);
    cudaFuncSetAttribute(av_mma_kernel,     cudaFuncAttributeMaxDynamicSharedMemorySize, SMEM_SZ);

    prep_w_kernel<<<4608, 256>>>(w1, w2);
    prep_refT_kernel<<<dim3(128, 8, B_), dim3(32, 8)>>>(ref);
    conv_mma_kernel<<<dim3(32, 4, B_), NT, SMEM_SZ>>>();
    scores_mma_kernel<<<dim3(528, B_), NT, SMEM_SZ>>>();
    rowstats_kernel<<<dim3(4096, B_), 256>>>();
    av_mma_kernel<<<dim3(32, 2, B_), NT, SMEM_SZ>>>(ref, gamma, out);
}

// round 11
// speedup vs baseline: 2.2759x; 1.1954x over previous
#include <cuda_runtime.h>
#include <cuda_fp16.h>
#include <cstdint>

#define HW_  4096
#define C_   256
#define B_   4
#define NT   128

// ---------------- scratch (__device__ globals per allocation rules) --------
__device__ __align__(1024) __half g_refT[B_ * HW_ * C_];  // [b*4096+pos][ci]
__device__ __align__(1024) __half g_w[2 * 9 * C_ * C_];   // [w][s][co][ci]
__device__ __align__(1024) __half g_x1t[B_ * HW_ * C_];   // [b*4096+pos][c]
__device__ __align__(1024) __half g_V[B_ * C_ * HW_];     // [b][c][pos]
__device__ __align__(1024) __half g_E[(size_t)B_ * HW_ * HW_]; // exp(S-mx) [m][n]
__device__ float g_S[(size_t)B_ * HW_ * HW_];
__device__ float g_rcp[B_ * HW_];

// ---------------- smem: 3 pipeline stages + aux ----------------------------
// stage s at s*32768: A +0, B +16K (each 128 rows x 128B, SW128)
// epilogue fp32 staging st[128][129] aliases stages; aux @98304
#define SM_A  0
#define SM_B  16384
#define STG   32768
#define NSTG  3
#define SM_AUX 98304
#define SMEM_SZ 99328

__device__ __forceinline__ uint32_t smem_u32(const void* p) {
    uint32_t a;
    asm("{ .reg .u64 t; cvta.to.shared.u64 t, %1; cvt.u32.u64 %0, t; }" : "=r"(a) : "l"(p));
    return a;
}
#define SW128(o) ((o) ^ (((o) >> 3) & 0x70))

__device__ __forceinline__ void cpa16(uint32_t dst, const void* src) {
    asm volatile("cp.async.cg.shared.global [%0], [%1], 16;" :: "r"(dst), "l"(src));
}
__device__ __forceinline__ void cpa16z(uint32_t dst, const void* src, bool v) {
    int sz = v ? 16 : 0;
    asm volatile("cp.async.cg.shared.global [%0], [%1], 16, %2;" :: "r"(dst), "l"(src), "r"(sz));
}
#define CP_COMMIT() asm volatile("cp.async.commit_group;" ::: "memory")
#define CP_WAIT1()  asm volatile("cp.async.wait_group 1;" ::: "memory")
#define CP_WAIT0()  asm volatile("cp.async.wait_group 0;" ::: "memory")

__device__ __forceinline__ void ldm4(uint32_t r[4], uint32_t addr) {
    asm volatile("ldmatrix.sync.aligned.m8n8.x4.shared.b16 {%0,%1,%2,%3}, [%4];"
        : "=r"(r[0]), "=r"(r[1]), "=r"(r[2]), "=r"(r[3]) : "r"(addr));
}
__device__ __forceinline__ void mma_f16(float d[4], const uint32_t a[4],
                                        uint32_t b0, uint32_t b1) {
    asm volatile("mma.sync.aligned.m16n8k16.row.col.f32.f16.f16.f32 "
        "{%0,%1,%2,%3}, {%4,%5,%6,%7}, {%8,%9}, {%0,%1,%2,%3};"
        : "+f"(d[0]), "+f"(d[1]), "+f"(d[2]), "+f"(d[3])
        : "r"(a[0]), "r"(a[1]), "r"(a[2]), "r"(a[3]), "r"(b0), "r"(b1));
}

// fp16 K=64 chunk on one 64x64 warp tile (4 m-frags x 8 n-frags)
__device__ __forceinline__ void warp_chunk1(float acc[4][8][4],
    uint32_t sA, uint32_t sB, int wm, int wn, int lane)
{
    const int tile = lane >> 3, tr = lane & 7;
    #pragma unroll
    for (int kk = 0; kk < 4; kk++) {
        uint32_t a[4][4];
        #pragma unroll
        for (int mf = 0; mf < 4; mf++) {
            int row = wm + mf * 16 + ((tile & 1) << 3) + tr;
            int g   = 2 * kk + (tile >> 1);
            ldm4(a[mf], sA + SW128((uint32_t)(row * 128 + g * 16)));
        }
        #pragma unroll
        for (int nf = 0; nf < 8; nf += 2) {
            int row = wn + nf * 8 + ((tile >> 1) << 3) + tr;
            int g   = 2 * kk + (tile & 1);
            uint32_t b[4];
            ldm4(b, sB + SW128((uint32_t)(row * 128 + g * 16)));
            #pragma unroll
            for (int mf = 0; mf < 4; mf++) {
                mma_f16(acc[mf][nf],     a[mf], b[0], b[1]);
                mma_f16(acc[mf][nf + 1], a[mf], b[2], b[3]);
            }
        }
    }
}

// accumulators -> fp32 staging st[m*129+n]
__device__ __forceinline__ void acc_to_staging(float* st, float acc[4][8][4],
                                               int wm, int wn, int lane, bool relu) {
    const int r0 = lane >> 2, c0 = (lane & 3) * 2;
    #pragma unroll
    for (int mf = 0; mf < 4; mf++)
        #pragma unroll
        for (int nf = 0; nf < 8; nf++)
            #pragma unroll
            for (int i = 0; i < 4; i++) {
                int m = wm + mf * 16 + r0 + (i >> 1) * 8;
                int n = wn + nf * 8 + c0 + (i & 1);
                float v = acc[mf][nf][i];
                st[m * 129 + n] = relu ? fmaxf(v, 0.0f) : v;
            }
}

// async 128x64 fp16 K-major tile fill (swizzled), rstride in elements, NT=128
__device__ __forceinline__ void fill64_async(uint32_t dst, const __half* src, int rstride) {
    int t = threadIdx.x;
    #pragma unroll
    for (int i = 0; i < 8; i++) {
        int idx = t + i * NT, r = idx >> 3, ch = idx & 7;
        cpa16(dst + SW128((uint32_t)(r * 128 + ch * 16)),
              src + (size_t)r * rstride + ch * 8);
    }
}

__device__ __forceinline__ float fast_exp(float x) {
    x = fmaxf(x, -87.0f);
    float y  = x * 1.4426950408889634f;
    float fl = floorf(y);
    float t  = (y - fl) * 0.6931471805599453f;
    float p = 1.3888889e-3f;
    p = fmaf(p, t, 8.3333333e-3f);
    p = fmaf(p, t, 4.1666667e-2f);
    p = fmaf(p, t, 1.6666667e-1f);
    p = fmaf(p, t, 0.5f);
    p = fmaf(p, t, 1.0f);
    p = fmaf(p, t, 1.0f);
    return __int_as_float(((int)fl + 127) << 23) * p;
}

// ---------------- prep: weights -> [w][s][co][ci] fp16 ---------------------
__global__ __launch_bounds__(256) void prep_w_kernel(
    const float* __restrict__ w1, const float* __restrict__ w2)
{
    int idx = blockIdx.x * 256 + threadIdx.x;        // < 1179648
    int w = idx / 589824, r = idx - w * 589824;
    int s = r >> 16, r2 = r & 65535, co = r2 >> 8, ci = r2 & 255;
    const float* wp = w ? w2 : w1;
    g_w[idx] = __float2half_rn(wp[co * 2304 + ci * 9 + s]);
}

// ---------------- prep: ref [b][c][pos] -> refT [b][pos][ci] fp16 ----------
__global__ void prep_refT_kernel(const float* __restrict__ ref)
{
    __shared__ float tile[32][33];
    int b = blockIdx.z, p0 = blockIdx.x * 32, c0 = blockIdx.y * 32;
    int x = threadIdx.x, y = threadIdx.y;            // (32, 8)
    #pragma unroll
    for (int i = 0; i < 4; i++)
        tile[y + i * 8][x] = ref[((size_t)(b * 256 + c0 + y + i * 8)) * 4096 + p0 + x];
    __syncthreads();
    #pragma unroll
    for (int i = 0; i < 4; i++) {
        int p = y + i * 8;
        g_refT[((size_t)((b << 12) + p0 + p)) * 256 + c0 + x] =
            __float2half_rn(tile[x][p]);
    }
}

// ---------------- conv 3x3 SAME + relu, 3-stage pipelined mma.sync ---------
// grid (32 pos-tiles, 4 = w*2+half, B_). D[co 128][pos 128]. 36 K-chunks.
__global__ __launch_bounds__(NT, 2) void conv_mma_kernel()
{
    extern __shared__ char sm[];
    const uint32_t sb = smem_u32(sm);
    const int t = threadIdx.x, lane = t & 31, wid = t >> 5;
    const int wm = (wid & 1) * 64, wn = (wid >> 1) * 64;
    const int pos0 = blockIdx.x * 128;
    const int w = blockIdx.y >> 1, half = blockIdx.y & 1;
    const int b = blockIdx.z;
    float acc[4][8][4] = {};

    auto do_fill = [&](int kc, int stg) {
        int s = kc >> 2, cc = kc & 3, ci0 = cc * 64;
        int dy = s / 3 - 1, dx = s % 3 - 1, shift = dy * 64 + dx;
        uint32_t base = sb + stg * STG;
        const size_t wbase = ((size_t)((w * 9 + s) * 256 + half * 128)) * 256 + ci0;
        #pragma unroll
        for (int i = 0; i < 8; i++) {
            int idx = t + i * NT, r = idx >> 3, ch = idx & 7;
            cpa16(base + SM_A + SW128((uint32_t)(r * 128 + ch * 16)),
                  g_w + wbase + (size_t)r * 256 + ch * 8);
        }
        #pragma unroll
        for (int i = 0; i < 8; i++) {
            int idx = t + i * NT, r = idx >> 3, ch = idx & 7;
            int pos = pos0 + r, y = pos >> 6, x = pos & 63;
            int yy = y + dy, xx = x + dx;
            bool valid = ((unsigned)yy < 64u) && ((unsigned)xx < 64u);
            long long so = valid ?
                ((long long)((b << 12) + pos + shift)) * 256 + ci0 + ch * 8 : 0;
            cpa16z(base + SM_B + SW128((uint32_t)(r * 128 + ch * 16)), g_refT + so, valid);
        }
    };

    do_fill(0, 0); CP_COMMIT();
    do_fill(1, 1); CP_COMMIT();
    for (int kc = 0; kc < 36; kc++) {
        CP_WAIT1();
        __syncthreads();
        if (kc + 2 < 36) do_fill(kc + 2, (kc + 2) % NSTG);
        CP_COMMIT();
        uint32_t base = sb + (kc % NSTG) * STG;
        warp_chunk1(acc, base + SM_A, base + SM_B, wm, wn, lane);
    }
    CP_WAIT0();
    __syncthreads();

    // epilogue: relu, write x1t (w=0) or V (w=1) as fp16
    float* st = (float*)sm;
    acc_to_staging(st, acc, wm, wn, lane, true);
    __syncthreads();
    if (w == 0) {
        for (int i = t; i < 16384; i += NT) {
            int p = i >> 7, c = i & 127;      // coalesced over c
            g_x1t[((size_t)((b << 12) + pos0 + p)) * 256 + half * 128 + c] =
                __float2half_rn(st[c * 129 + p]);
        }
    } else {
        for (int i = t; i < 16384; i += NT) {
            int c = i >> 7, p = i & 127;      // coalesced over p
            g_V[((size_t)((b << 8) + half * 128 + c)) * 4096 + pos0 + p] =
                __float2half_rn(st[c * 129 + p]);
        }
    }
}

// ---------------- scores = x1t . x1t^T (symmetric, triangular grid) --------
__global__ __launch_bounds__(NT, 2) void scores_mma_kernel()
{
    extern __shared__ char sm[];
    const uint32_t sb = smem_u32(sm);
    const int t = threadIdx.x, lane = t & 31, wid = t >> 5;
    const int wm = (wid & 1) * 64, wn = (wid >> 1) * 64;
    const int b = blockIdx.y;
    int i = 0, pp = blockIdx.x;
    while (pp >= 32 - i) { pp -= 32 - i; i++; }
    const int n0 = i * 128, m0 = (i + pp) * 128;
    float acc[4][8][4] = {};

    auto do_fill = [&](int kc, int stg) {
        int k0 = kc * 64;
        uint32_t base = sb + stg * STG;
        fill64_async(base + SM_A, g_x1t + ((size_t)((b << 12) + n0)) * 256 + k0, 256);
        fill64_async(base + SM_B, g_x1t + ((size_t)((b << 12) + m0)) * 256 + k0, 256);
    };

    do_fill(0, 0); CP_COMMIT();
    do_fill(1, 1); CP_COMMIT();
    for (int kc = 0; kc < 4; kc++) {
        CP_WAIT1();
        __syncthreads();
        if (kc + 2 < 4) do_fill(kc + 2, (kc + 2) % NSTG);
        CP_COMMIT();
        uint32_t base = sb + (kc % NSTG) * STG;
        warp_chunk1(acc, base + SM_A, base + SM_B, wm, wn, lane);
    }
    CP_WAIT0();
    __syncthreads();

    float* st = (float*)sm;
    acc_to_staging(st, acc, wm, wn, lane, false);
    __syncthreads();
    float* Sb = g_S + (size_t)b * HW_ * HW_;
    for (int ii = t; ii < 16384; ii += NT) {
        int r = ii >> 7, c = ii & 127;
        Sb[(size_t)(n0 + r) * 4096 + m0 + c] = st[r * 129 + c];
    }
    if (n0 != m0) {
        for (int ii = t; ii < 16384; ii += NT) {
            int r = ii >> 7, c = ii & 127;
            Sb[(size_t)(m0 + r) * 4096 + n0 + c] = st[c * 129 + r];
        }
    }
}

// ---------------- row stats + E materialization (fp16) ---------------------
// By symmetry row stats == column stats. E[m][n] = exp(S[m][n] - mx[m]).
__global__ __launch_bounds__(256) void rowstats_kernel()
{
    __shared__ float red[256];
    const int b = blockIdx.y, m = blockIdx.x, t = threadIdx.x;
    const float* __restrict__ row = g_S + ((size_t)b * HW_ + m) * HW_;
    float4 v[4];
    #pragma unroll
    for (int i = 0; i < 4; i++) v[i] = *(const float4*)(row + i * 1024 + t * 4);
    float mx = -1e30f;
    #pragma unroll
    for (int i = 0; i < 4; i++)
        mx = fmaxf(mx, fmaxf(fmaxf(v[i].x, v[i].y), fmaxf(v[i].z, v[i].w)));
    red[t] = mx;
    __syncthreads();
    #pragma unroll
    for (int s = 128; s >= 32; s >>= 1) {
        if (t < s) red[t] = fmaxf(red[t], red[t + s]);
        __syncthreads();
    }
    if (t < 32) {
        float r = red[t];
        #pragma unroll
        for (int o = 16; o > 0; o >>= 1) r = fmaxf(r, __shfl_xor_sync(~0u, r, o));
        red[0] = r;
    }
    __syncthreads();
    mx = red[0];
    __syncthreads();
    float sum = 0.0f;
    #pragma unroll
    for (int i = 0; i < 4; i++) {
        float vv[4] = {v[i].x, v[i].y, v[i].z, v[i].w};
        __half hh[4];
        #pragma unroll
        for (int j = 0; j < 4; j++) {
            float e = fast_exp(vv[j] - mx);
            sum += e;
            hh[j] = __float2half_rn(e);
        }
        size_t eo = ((size_t)((b << 12) + m)) * 4096 + i * 1024 + t * 4;
        *(uint2*)(g_E + eo) = *(uint2*)hh;
    }
    red[t] = sum;
    __syncthreads();
    #pragma unroll
    for (int s = 128; s >= 32; s >>= 1) {
        if (t < s) red[t] += red[t + s];
        __syncthreads();
    }
    if (t < 32) {
        float r = red[t];
        #pragma unroll
        for (int o = 16; o > 0; o >>= 1) r += __shfl_xor_sync(~0u, r, o);
        if (t == 0) g_rcp[b * HW_ + m] = 1.0f / r;
    }
}

// ---------------- AV: out = gamma * rcp[m] * (V . E^T) + ref ---------------
// grid (32 m-tiles, 2 c-halves, B_). Pure pipelined GEMM, K = n (4096).
__global__ __launch_bounds__(NT, 2) void av_mma_kernel(
    const float* __restrict__ ref, const float* __restrict__ gamma_p,
    float* __restrict__ out)
{
    extern __shared__ char sm[];
    const uint32_t sb = smem_u32(sm);
    const int t = threadIdx.x, lane = t & 31, wid = t >> 5;
    const int wm = (wid & 1) * 64, wn = (wid >> 1) * 64;
    const int m0 = blockIdx.x * 128, chalf = blockIdx.y, b = blockIdx.z;
    float acc[4][8][4] = {};

    auto do_fill = [&](int kc, int stg) {
        int k0 = kc * 64;
        uint32_t base = sb + stg * STG;
        fill64_async(base + SM_A,
                     g_V + ((size_t)((b << 8) + chalf * 128)) * 4096 + k0, 4096);
        fill64_async(base + SM_B,
                     g_E + ((size_t)((b << 12) + m0)) * 4096 + k0, 4096);
    };

    do_fill(0, 0); CP_COMMIT();
    do_fill(1, 1); CP_COMMIT();
    for (int kc = 0; kc < 64; kc++) {
        CP_WAIT1();
        __syncthreads();
        if (kc + 2 < 64) do_fill(kc + 2, (kc + 2) % NSTG);
        CP_COMMIT();
        uint32_t base = sb + (kc % NSTG) * STG;
        warp_chunk1(acc, base + SM_A, base + SM_B, wm, wn, lane);
    }
    CP_WAIT0();
    __syncthreads();

    // epilogue
    float* st = (float*)sm;
    acc_to_staging(st, acc, wm, wn, lane, false);
    float* s_rc = (float*)(sm + SM_AUX);
    if (t < 128) s_rc[t] = (*gamma_p) * g_rcp[(b << 12) + m0 + t];
    __syncthreads();
    for (int ii = t; ii < 16384; ii += NT) {
        int cl = ii >> 7, n = ii & 127;       // coalesced over n
        size_t o = ((size_t)((b << 8) + chalf * 128 + cl)) * 4096 + m0 + n;
        out[o] = fmaf(st[cl * 129 + n], s_rc[n], ref[o]);
    }
}

// ---------------------------------------------------------------------------
extern "C" void kernel_launch(void* const* d_in, const int* in_sizes, int n_in,
                              void* d_out, int out_size)
{
    const float* ref   = (const float*)d_in[1];   // d_in[0] 'inputs' is dead in reference
    const float* w1    = (const float*)d_in[2];
    const float* w2    = (const float*)d_in[3];
    const float* gamma = (const float*)d_in[4];
    float* out = (float*)d_out;

    cudaFuncSetAttribute(conv_mma_kernel,   cudaFuncAttributeMaxDynamicSharedMemorySize, SMEM_SZ);
    cudaFuncSetAttribute(scores_mma_kernel, cudaFuncAttributeMaxDynamicSharedMemorySize, SMEM_SZ);
    cudaFuncSetAttribute(av_mma_kernel,     cudaFuncAttributeMaxDynamicSharedMemorySize, SMEM_SZ);

    prep_w_kernel<<<4608, 256>>>(w1, w2);
    prep_refT_kernel<<<dim3(128, 8, B_), dim3(32, 8)>>>(ref);
    conv_mma_kernel<<<dim3(32, 4, B_), NT, SMEM_SZ>>>();
    scores_mma_kernel<<<dim3(528, B_), NT, SMEM_SZ>>>();
    rowstats_kernel<<<dim3(4096, B_), 256>>>();
    av_mma_kernel<<<dim3(32, 2, B_), NT, SMEM_SZ>>>(ref, gamma, out);
}

// round 12
// speedup vs baseline: 2.3082x; 1.0142x over previous
#include <cuda_runtime.h>
#include <cuda_fp16.h>
#include <cstdint>

#define HW_  4096
#define C_   256
#define B_   4

// ---------------- scratch (__device__ globals per allocation rules) --------
__device__ __align__(1024) __half g_refT[B_ * HW_ * C_];  // [b*4096+pos][ci]
__device__ __align__(1024) __half g_w[2 * 9 * C_ * C_];   // [w][s][co][ci]
__device__ __align__(1024) __half g_x1t[B_ * HW_ * C_];   // [b*4096+pos][c]
__device__ __align__(1024) __half g_V[B_ * C_ * HW_];     // [b][c][pos]
__device__ __align__(1024) __half g_E[(size_t)B_ * HW_ * HW_]; // exp(S-mx) [m][n]
__device__ __align__(1024) __half g_S[(size_t)B_ * HW_ * HW_]; // scores fp16 [n][m]
__device__ float g_rcp[B_ * HW_];

// ---------------- smem layouts ---------------------------------------------
// scores (128 thr): stage s at s*32768: A +0 (16K), B +16K. 3 stages. aux @98304.
#define SC_SM_A 0
#define SC_SM_B 16384
#define SC_STG  32768
#define SC_NSTG 3
#define SC_SMEM 99328
// conv/av (256 thr): stage s at s*49152: A +0 (32K, 256 rows), B +32K (16K).
#define CV_SM_A 0
#define CV_SM_B 32768
#define CV_STG  49152
#define CV_NSTG 3
#define CV_AUX  147456
#define CV_SMEM 148480

__device__ __forceinline__ uint32_t smem_u32(const void* p) {
    uint32_t a;
    asm("{ .reg .u64 t; cvta.to.shared.u64 t, %1; cvt.u32.u64 %0, t; }" : "=r"(a) : "l"(p));
    return a;
}
#define SW128(o) ((o) ^ (((o) >> 3) & 0x70))

__device__ __forceinline__ void cpa16(uint32_t dst, const void* src) {
    asm volatile("cp.async.cg.shared.global [%0], [%1], 16;" :: "r"(dst), "l"(src));
}
__device__ __forceinline__ void cpa16z(uint32_t dst, const void* src, bool v) {
    int sz = v ? 16 : 0;
    asm volatile("cp.async.cg.shared.global [%0], [%1], 16, %2;" :: "r"(dst), "l"(src), "r"(sz));
}
#define CP_COMMIT() asm volatile("cp.async.commit_group;" ::: "memory")
#define CP_WAIT1()  asm volatile("cp.async.wait_group 1;" ::: "memory")
#define CP_WAIT0()  asm volatile("cp.async.wait_group 0;" ::: "memory")

__device__ __forceinline__ void ldm4(uint32_t r[4], uint32_t addr) {
    asm volatile("ldmatrix.sync.aligned.m8n8.x4.shared.b16 {%0,%1,%2,%3}, [%4];"
        : "=r"(r[0]), "=r"(r[1]), "=r"(r[2]), "=r"(r[3]) : "r"(addr));
}
__device__ __forceinline__ void mma_f16(float d[4], const uint32_t a[4],
                                        uint32_t b0, uint32_t b1) {
    asm volatile("mma.sync.aligned.m16n8k16.row.col.f32.f16.f16.f32 "
        "{%0,%1,%2,%3}, {%4,%5,%6,%7}, {%8,%9}, {%0,%1,%2,%3};"
        : "+f"(d[0]), "+f"(d[1]), "+f"(d[2]), "+f"(d[3])
        : "r"(a[0]), "r"(a[1]), "r"(a[2]), "r"(a[3]), "r"(b0), "r"(b1));
}

// fp16 K=64 chunk on one 64x64 warp tile (4 m-frags x 8 n-frags)
__device__ __forceinline__ void warp_chunk1(float acc[4][8][4],
    uint32_t sA, uint32_t sB, int wm, int wn, int lane)
{
    const int tile = lane >> 3, tr = lane & 7;
    #pragma unroll
    for (int kk = 0; kk < 4; kk++) {
        uint32_t a[4][4];
        #pragma unroll
        for (int mf = 0; mf < 4; mf++) {
            int row = wm + mf * 16 + ((tile & 1) << 3) + tr;
            int g   = 2 * kk + (tile >> 1);
            ldm4(a[mf], sA + SW128((uint32_t)(row * 128 + g * 16)));
        }
        #pragma unroll
        for (int nf = 0; nf < 8; nf += 2) {
            int row = wn + nf * 8 + ((tile >> 1) << 3) + tr;
            int g   = 2 * kk + (tile & 1);
            uint32_t b[4];
            ldm4(b, sB + SW128((uint32_t)(row * 128 + g * 16)));
            #pragma unroll
            for (int mf = 0; mf < 4; mf++) {
                mma_f16(acc[mf][nf],     a[mf], b[0], b[1]);
                mma_f16(acc[mf][nf + 1], a[mf], b[2], b[3]);
            }
        }
    }
}

// accumulators -> fp32 staging st[m*129+n] (wm is LOCAL 0..64)
__device__ __forceinline__ void acc_to_staging(float* st, float acc[4][8][4],
                                               int wm, int wn, int lane, bool relu) {
    const int r0 = lane >> 2, c0 = (lane & 3) * 2;
    #pragma unroll
    for (int mf = 0; mf < 4; mf++)
        #pragma unroll
        for (int nf = 0; nf < 8; nf++)
            #pragma unroll
            for (int i = 0; i < 4; i++) {
                int m = wm + mf * 16 + r0 + (i >> 1) * 8;
                int n = wn + nf * 8 + c0 + (i & 1);
                float v = acc[mf][nf][i];
                st[m * 129 + n] = relu ? fmaxf(v, 0.0f) : v;
            }
}

__device__ __forceinline__ float fast_exp(float x) {
    x = fmaxf(x, -87.0f);
    float y  = x * 1.4426950408889634f;
    float fl = floorf(y);
    float t  = (y - fl) * 0.6931471805599453f;
    float p = 1.3888889e-3f;
    p = fmaf(p, t, 8.3333333e-3f);
    p = fmaf(p, t, 4.1666667e-2f);
    p = fmaf(p, t, 1.6666667e-1f);
    p = fmaf(p, t, 0.5f);
    p = fmaf(p, t, 1.0f);
    p = fmaf(p, t, 1.0f);
    return __int_as_float(((int)fl + 127) << 23) * p;
}

// ---------------- prep: weights -> [w][s][co][ci] fp16 ---------------------
__global__ __launch_bounds__(256) void prep_w_kernel(
    const float* __restrict__ w1, const float* __restrict__ w2)
{
    int idx = blockIdx.x * 256 + threadIdx.x;        // < 1179648
    int w = idx / 589824, r = idx - w * 589824;
    int s = r >> 16, r2 = r & 65535, co = r2 >> 8, ci = r2 & 255;
    const float* wp = w ? w2 : w1;
    g_w[idx] = __float2half_rn(wp[co * 2304 + ci * 9 + s]);
}

// ---------------- prep: ref [b][c][pos] -> refT [b][pos][ci] fp16 ----------
__global__ void prep_refT_kernel(const float* __restrict__ ref)
{
    __shared__ float tile[32][33];
    int b = blockIdx.z, p0 = blockIdx.x * 32, c0 = blockIdx.y * 32;
    int x = threadIdx.x, y = threadIdx.y;            // (32, 8)
    #pragma unroll
    for (int i = 0; i < 4; i++)
        tile[y + i * 8][x] = ref[((size_t)(b * 256 + c0 + y + i * 8)) * 4096 + p0 + x];
    __syncthreads();
    #pragma unroll
    for (int i = 0; i < 4; i++) {
        int p = y + i * 8;
        g_refT[((size_t)((b << 12) + p0 + p)) * 256 + c0 + x] =
            __float2half_rn(tile[x][p]);
    }
}

// ---------------- conv 3x3 SAME + relu: both weights fused -----------------
// grid (32 pos-tiles, 2 co-half, B_). M=256 stacked [w1,w2], N=128 pos.
__global__ __launch_bounds__(256, 1) void conv_mma_kernel()
{
    extern __shared__ char sm[];
    const uint32_t sb = smem_u32(sm);
    const int t = threadIdx.x, lane = t & 31, wid = t >> 5;
    const int wm = (wid & 3) * 64, wn = (wid >> 2) * 64;
    const int pos0 = blockIdx.x * 128;
    const int half = blockIdx.y;
    const int b = blockIdx.z;
    float acc[4][8][4] = {};

    auto do_fill = [&](int kc, int stg) {
        int s = kc >> 2, cc = kc & 3, ci0 = cc * 64;
        int dy = s / 3 - 1, dx = s % 3 - 1, shift = dy * 64 + dx;
        uint32_t base = sb + stg * CV_STG;
        #pragma unroll
        for (int i = 0; i < 8; i++) {
            int idx = t + i * 256, r = idx >> 3, ch = idx & 7;
            int w = r >> 7, co = half * 128 + (r & 127);
            cpa16(base + CV_SM_A + SW128((uint32_t)(r * 128 + ch * 16)),
                  g_w + ((size_t)((w * 9 + s) * 256 + co)) * 256 + ci0 + ch * 8);
        }
        #pragma unroll
        for (int i = 0; i < 4; i++) {
            int idx = t + i * 256, r = idx >> 3, ch = idx & 7;
            int pos = pos0 + r, y = pos >> 6, x = pos & 63;
            int yy = y + dy, xx = x + dx;
            bool valid = ((unsigned)yy < 64u) && ((unsigned)xx < 64u);
            long long so = valid ?
                ((long long)((b << 12) + pos + shift)) * 256 + ci0 + ch * 8 : 0;
            cpa16z(base + CV_SM_B + SW128((uint32_t)(r * 128 + ch * 16)), g_refT + so, valid);
        }
    };

    do_fill(0, 0); CP_COMMIT();
    do_fill(1, 1); CP_COMMIT();
    for (int kc = 0; kc < 36; kc++) {
        CP_WAIT1();
        __syncthreads();
        if (kc + 2 < 36) do_fill(kc + 2, (kc + 2) % CV_NSTG);
        CP_COMMIT();
        uint32_t base = sb + (kc % CV_NSTG) * CV_STG;
        warp_chunk1(acc, base + CV_SM_A, base + CV_SM_B, wm, wn, lane);
    }
    CP_WAIT0();

    // epilogue: relu, pass 0 -> x1t (w1), pass 1 -> V (w2)
    float* st = (float*)sm;
    for (int pass = 0; pass < 2; pass++) {
        __syncthreads();
        if ((wm >> 7) == pass)
            acc_to_staging(st, acc, wm & 127, wn, lane, true);
        __syncthreads();
        if (pass == 0) {
            for (int i = t; i < 16384; i += 256) {
                int p = i >> 7, c = i & 127;      // coalesced over c
                g_x1t[((size_t)((b << 12) + pos0 + p)) * 256 + half * 128 + c] =
                    __float2half_rn(st[c * 129 + p]);
            }
        } else {
            for (int i = t; i < 16384; i += 256) {
                int c = i >> 7, p = i & 127;      // coalesced over p
                g_V[((size_t)((b << 8) + half * 128 + c)) * 4096 + pos0 + p] =
                    __float2half_rn(st[c * 129 + p]);
            }
        }
    }
}

// ---------------- scores = x1t . x1t^T (symmetric, triangular grid) --------
__global__ __launch_bounds__(128, 2) void scores_mma_kernel()
{
    extern __shared__ char sm[];
    const uint32_t sb = smem_u32(sm);
    const int t = threadIdx.x, lane = t & 31, wid = t >> 5;
    const int wm = (wid & 1) * 64, wn = (wid >> 1) * 64;
    const int b = blockIdx.y;
    int i = 0, pp = blockIdx.x;
    while (pp >= 32 - i) { pp -= 32 - i; i++; }
    const int n0 = i * 128, m0 = (i + pp) * 128;
    float acc[4][8][4] = {};

    auto do_fill = [&](int kc, int stg) {
        int k0 = kc * 64;
        uint32_t base = sb + stg * SC_STG;
        #pragma unroll
        for (int ii2 = 0; ii2 < 8; ii2++) {
            int idx = t + ii2 * 128, r = idx >> 3, ch = idx & 7;
            uint32_t sw = SW128((uint32_t)(r * 128 + ch * 16));
            cpa16(base + SC_SM_A + sw,
                  g_x1t + ((size_t)((b << 12) + n0 + r)) * 256 + k0 + ch * 8);
            cpa16(base + SC_SM_B + sw,
                  g_x1t + ((size_t)((b << 12) + m0 + r)) * 256 + k0 + ch * 8);
        }
    };

    do_fill(0, 0); CP_COMMIT();
    do_fill(1, 1); CP_COMMIT();
    for (int kc = 0; kc < 4; kc++) {
        CP_WAIT1();
        __syncthreads();
        if (kc + 2 < 4) do_fill(kc + 2, (kc + 2) % SC_NSTG);
        CP_COMMIT();
        uint32_t base = sb + (kc % SC_NSTG) * SC_STG;
        warp_chunk1(acc, base + SC_SM_A, base + SC_SM_B, wm, wn, lane);
    }
    CP_WAIT0();
    __syncthreads();

    float* st = (float*)sm;
    acc_to_staging(st, acc, wm, wn, lane, false);
    __syncthreads();
    __half* Sb = g_S + (size_t)b * HW_ * HW_;
    for (int ii2 = t; ii2 < 16384; ii2 += 128) {
        int r = ii2 >> 7, c = ii2 & 127;
        Sb[(size_t)(n0 + r) * 4096 + m0 + c] = __float2half_rn(st[r * 129 + c]);
    }
    if (n0 != m0) {
        for (int ii2 = t; ii2 < 16384; ii2 += 128) {
            int r = ii2 >> 7, c = ii2 & 127;
            Sb[(size_t)(m0 + r) * 4096 + n0 + c] = __float2half_rn(st[c * 129 + r]);
        }
    }
}

// ---------------- row stats + E materialization (fp16 S in, fp16 E out) ----
__global__ __launch_bounds__(256) void rowstats_kernel()
{
    __shared__ float red[256];
    const int b = blockIdx.y, m = blockIdx.x, t = threadIdx.x;
    const __half* __restrict__ row = g_S + ((size_t)b * HW_ + m) * HW_;

    union { uint4 u; __half h[8]; } cv[2];
    float v[16];
    #pragma unroll
    for (int i = 0; i < 2; i++) {
        cv[i].u = ((const uint4*)row)[t + i * 256];
        #pragma unroll
        for (int j = 0; j < 8; j++) v[i * 8 + j] = __half2float(cv[i].h[j]);
    }
    float mx = -1e30f;
    #pragma unroll
    for (int i = 0; i < 16; i++) mx = fmaxf(mx, v[i]);
    red[t] = mx;
    __syncthreads();
    #pragma unroll
    for (int s = 128; s >= 32; s >>= 1) {
        if (t < s) red[t] = fmaxf(red[t], red[t + s]);
        __syncthreads();
    }
    if (t < 32) {
        float r = red[t];
        #pragma unroll
        for (int o = 16; o > 0; o >>= 1) r = fmaxf(r, __shfl_xor_sync(~0u, r, o));
        red[0] = r;
    }
    __syncthreads();
    mx = red[0];
    __syncthreads();
    float sum = 0.0f;
    #pragma unroll
    for (int i = 0; i < 2; i++) {
        union { uint4 u; __half h[8]; } ev;
        #pragma unroll
        for (int j = 0; j < 8; j++) {
            float e = fast_exp(v[i * 8 + j] - mx);
            sum += e;
            ev.h[j] = __float2half_rn(e);
        }
        ((uint4*)(g_E + ((size_t)((b << 12) + m)) * 4096))[t + i * 256] = ev.u;
    }
    red[t] = sum;
    __syncthreads();
    #pragma unroll
    for (int s = 128; s >= 32; s >>= 1) {
        if (t < s) red[t] += red[t + s];
        __syncthreads();
    }
    if (t < 32) {
        float r = red[t];
        #pragma unroll
        for (int o = 16; o > 0; o >>= 1) r += __shfl_xor_sync(~0u, r, o);
        if (t == 0) g_rcp[b * HW_ + m] = 1.0f / r;
    }
}

// ---------------- AV: out = gamma * rcp[m] * (V . E^T) + ref ---------------
// grid (32 m-tiles, B_). M=256 (all c), N=128 m, K = n (4096). E read ONCE.
__global__ __launch_bounds__(256, 1) void av_mma_kernel(
    const float* __restrict__ ref, const float* __restrict__ gamma_p,
    float* __restrict__ out)
{
    extern __shared__ char sm[];
    const uint32_t sb = smem_u32(sm);
    const int t = threadIdx.x, lane = t & 31, wid = t >> 5;
    const int wm = (wid & 3) * 64, wn = (wid >> 2) * 64;
    const int m0 = blockIdx.x * 128, b = blockIdx.y;
    float acc[4][8][4] = {};

    auto do_fill = [&](int kc, int stg) {
        int k0 = kc * 64;
        uint32_t base = sb + stg * CV_STG;
        #pragma unroll
        for (int i = 0; i < 8; i++) {
            int idx = t + i * 256, r = idx >> 3, ch = idx & 7;
            cpa16(base + CV_SM_A + SW128((uint32_t)(r * 128 + ch * 16)),
                  g_V + ((size_t)((b << 8) + r)) * 4096 + k0 + ch * 8);
        }
        #pragma unroll
        for (int i = 0; i < 4; i++) {
            int idx = t + i * 256, r = idx >> 3, ch = idx & 7;
            cpa16(base + CV_SM_B + SW128((uint32_t)(r * 128 + ch * 16)),
                  g_E + ((size_t)((b << 12) + m0 + r)) * 4096 + k0 + ch * 8);
        }
    };

    do_fill(0, 0); CP_COMMIT();
    do_fill(1, 1); CP_COMMIT();
    for (int kc = 0; kc < 64; kc++) {
        CP_WAIT1();
        __syncthreads();
        if (kc + 2 < 64) do_fill(kc + 2, (kc + 2) % CV_NSTG);
        CP_COMMIT();
        uint32_t base = sb + (kc % CV_NSTG) * CV_STG;
        warp_chunk1(acc, base + CV_SM_A, base + CV_SM_B, wm, wn, lane);
    }
    CP_WAIT0();

    // epilogue: two c-half passes through staging
    float* st = (float*)sm;
    float* s_rc = (float*)(sm + CV_AUX);
    if (t < 128) s_rc[t] = (*gamma_p) * g_rcp[(b << 12) + m0 + t];
    for (int pass = 0; pass < 2; pass++) {
        __syncthreads();
        if ((wm >> 7) == pass)
            acc_to_staging(st, acc, wm & 127, wn, lane, false);
        __syncthreads();
        for (int ii2 = t; ii2 < 16384; ii2 += 256) {
            int cl = ii2 >> 7, n = ii2 & 127;     // coalesced over n
            size_t o = ((size_t)((b << 8) + pass * 128 + cl)) * 4096 + m0 + n;
            out[o] = fmaf(st[cl * 129 + n], s_rc[n], ref[o]);
        }
    }
}

// ---------------------------------------------------------------------------
extern "C" void kernel_launch(void* const* d_in, const int* in_sizes, int n_in,
                              void* d_out, int out_size)
{
    const float* ref   = (const float*)d_in[1];   // d_in[0] 'inputs' is dead in reference
    const float* w1    = (const float*)d_in[2];
    const float* w2    = (const float*)d_in[3];
    const float* gamma = (const float*)d_in[4];
    float* out = (float*)d_out;

    cudaFuncSetAttribute(conv_mma_kernel,   cudaFuncAttributeMaxDynamicSharedMemorySize, CV_SMEM);
    cudaFuncSetAttribute(scores_mma_kernel, cudaFuncAttributeMaxDynamicSharedMemorySize, SC_SMEM);
    cudaFuncSetAttribute(av_mma_kernel,     cudaFuncAttributeMaxDynamicSharedMemorySize, CV_SMEM);

    prep_w_kernel<<<4608, 256>>>(w1, w2);
    prep_refT_kernel<<<dim3(128, 8, B_), dim3(32, 8)>>>(ref);
    conv_mma_kernel<<<dim3(32, 2, B_), 256, CV_SMEM>>>();
    scores_mma_kernel<<<dim3(528, B_), 128, SC_SMEM>>>();
    rowstats_kernel<<<dim3(4096, B_), 256>>>();
    av_mma_kernel<<<dim3(32, B_), 256, CV_SMEM>>>(ref, gamma, out);
}